// round 15
// baseline (speedup 1.0000x reference)
#include <cuda_runtime.h>
#include <cstdint>

// QLayerNorm: B=4, S=8192, D=1024, fp32. Warp-per-row, cp.async loads
// (R9 champion) + BULK-ASYNC STORES: output row is written back into the
// same smem buffer, then ONE cp.async.bulk (TMA-class) 4KB store per row
// moves the entire write stream to the async engine (full 128B bursts,
// no per-thread STG through the LSU). This is the last untested subsystem
// interaction: every prior variant (R3/R9/R12/R14; occ 21-51%) pinned at
// ~5.5TB/s on the mixed read/write stream with STG writes.
//
// Reference std recurrence (divisor is ALWAYS a, not the iterate):
//   l1=(a/a+a)*.5 ; l2=(l1/a+a)*.5 ; l3=(l2/a+a)*.5 ; std=(l3/a+a)*.5
// Implemented with inv_a = 1/a computed once (fp32 delta ~1e-7, tol 1e-3).

#define D 1024
#define WARPS_PER_CTA 8
#define THREADS (WARPS_PER_CTA * 32)
#define VPL 8            // float4 per lane (D / (32*4))
#define EPS 5e-05f

__global__ __launch_bounds__(THREADS) void qlayernorm_kernel(
    const float* __restrict__ x,
    const float* __restrict__ weight,
    const float* __restrict__ bias,
    float* __restrict__ out)
{
    __shared__ float4 sh[WARPS_PER_CTA][D / 4];   // 4KB per row, 32KB total

    const int warp = threadIdx.x >> 5;
    const int lane = threadIdx.x & 31;
    const int row  = blockIdx.x * WARPS_PER_CTA + warp;

    const float4* xr4 = reinterpret_cast<const float4*>(x + (long long)row * D);
    float*        orow = out + (long long)row * D;
    const float4* w4  = reinterpret_cast<const float4*>(weight);
    const float4* b4  = reinterpret_cast<const float4*>(bias);

    // ---- Stage row into smem: 8 async 16B copies per lane, no regs held ----
    #pragma unroll
    for (int i = 0; i < VPL; i++) {
        const int idx = i * 32 + lane;
        uint32_t dst = (uint32_t)__cvta_generic_to_shared(&sh[warp][idx]);
        asm volatile("cp.async.cg.shared.global [%0], [%1], 16;"
                     :: "r"(dst), "l"(xr4 + idx));
    }
    asm volatile("cp.async.commit_group;");
    asm volatile("cp.async.wait_all;" ::: "memory");
    // Each lane only reads its OWN slots back -> no cross-thread sync needed.

    // ---- Pass 1: accumulate sum / sumsq from smem ----
    float s = 0.0f, ss = 0.0f;
    #pragma unroll
    for (int i = 0; i < VPL; i++) {
        float4 v = sh[warp][i * 32 + lane];
        s  += v.x + v.y + v.z + v.w;
        ss += v.x * v.x + v.y * v.y + v.z * v.z + v.w * v.w;
    }

    // Butterfly reduction: every lane ends with the full row sums
    #pragma unroll
    for (int off = 16; off > 0; off >>= 1) {
        s  += __shfl_xor_sync(0xFFFFFFFFu, s,  off);
        ss += __shfl_xor_sync(0xFFFFFFFFu, ss, off);
    }

    // Scalar epilogue, redundant per lane
    const float inv_d = 1.0f / (float)D;
    float mean = s * inv_d;
    float var  = ss * inv_d - mean * mean;
    float a = var + EPS;
    float inv_a = 1.0f / a;            // single divide
    float half_a = 0.5f * a;
    float t;
    t = fmaf(a * inv_a, 0.5f, half_a);     // l1 = (a/a + a)*0.5
    t = fmaf(t * inv_a, 0.5f, half_a);     // l2
    t = fmaf(t * inv_a, 0.5f, half_a);     // l3
    t = fmaf(t * inv_a, 0.5f, half_a);     // std
    const float rstd = 1.0f / t;

    // ---- Pass 2: normalize + affine, write result back IN-PLACE to smem ----
    #pragma unroll
    for (int i = 0; i < VPL; i++) {
        const int idx = i * 32 + lane;
        float4 v = sh[warp][idx];       // LDS.128, own slot
        float4 w = w4[idx];
        float4 b = b4[idx];
        float4 o;
        o.x = (v.x - mean) * rstd * w.x + b.x;
        o.y = (v.y - mean) * rstd * w.y + b.y;
        o.z = (v.z - mean) * rstd * w.z + b.z;
        o.w = (v.w - mean) * rstd * w.w + b.w;
        sh[warp][idx] = o;              // STS.128, own slot (no hazard)
    }

    // ---- Single 4KB bulk-async store of the whole row (TMA engine) ----
    __syncwarp();
    asm volatile("fence.proxy.async.shared::cta;" ::: "memory");
    if (lane == 0) {
        uint32_t src = (uint32_t)__cvta_generic_to_shared(&sh[warp][0]);
        asm volatile(
            "cp.async.bulk.global.shared::cta.bulk_group [%0], [%1], %2;"
            :: "l"(orow), "r"(src), "r"(D * 4) : "memory");
        asm volatile("cp.async.bulk.commit_group;");
        asm volatile("cp.async.bulk.wait_group 0;" ::: "memory");
    }
}

extern "C" void kernel_launch(void* const* d_in, const int* in_sizes, int n_in,
                              void* d_out, int out_size) {
    const float* x      = (const float*)d_in[0];
    const float* weight = (const float*)d_in[1];
    const float* bias   = (const float*)d_in[2];
    float* out          = (float*)d_out;

    const int rows = in_sizes[0] / D;                 // 32768
    const int grid = rows / WARPS_PER_CTA;            // 4096
    qlayernorm_kernel<<<grid, THREADS>>>(x, weight, bias, out);
}

// round 16
// speedup vs baseline: 1.1166x; 1.1166x over previous
#include <cuda_runtime.h>

// QLayerNorm: B=4, S=8192, D=1024, fp32. FINAL — revert to the measured-best
// structure (R3): warp-per-row, row held in registers, no smem, no barriers.
// Seven structural variants (occupancy 21-67%, cp.async, double-buffering,
// stcs, bulk-async stores, persistent grid) all landed >= this kernel's
// 37.5us ncu time at ~5.5-5.7 TB/s: the kernel is pinned at the memory
// system's 1:1 read/write turnaround point, and this is the simplest
// structure that achieves it.
//
// Reference std recurrence (divisor is ALWAYS a, not the iterate):
//   l1=(a/a+a)*.5 ; l2=(l1/a+a)*.5 ; l3=(l2/a+a)*.5 ; std=(l3/a+a)*.5
// Implemented with inv_a = 1/a computed once (fp32 delta ~1e-7, tol 1e-3).

#define D 1024
#define WARPS_PER_CTA 8
#define THREADS (WARPS_PER_CTA * 32)
#define VPL 8            // float4 loads per lane (D / (32*4))
#define EPS 5e-05f

__global__ __launch_bounds__(THREADS) void qlayernorm_kernel(
    const float* __restrict__ x,
    const float* __restrict__ weight,
    const float* __restrict__ bias,
    float* __restrict__ out)
{
    const int warp = threadIdx.x >> 5;
    const int lane = threadIdx.x & 31;
    const int row  = blockIdx.x * WARPS_PER_CTA + warp;

    const float* xr   = x   + (long long)row * D;
    float*       orow = out + (long long)row * D;

    // Front-batched loads: 8 independent float4 -> 32 outstanding lines/warp
    float4 v[VPL];
    #pragma unroll
    for (int i = 0; i < VPL; i++) {
        v[i] = *reinterpret_cast<const float4*>(xr + (i * 32 + lane) * 4);
    }

    // Per-lane partial sums
    float s = 0.0f, ss = 0.0f;
    #pragma unroll
    for (int i = 0; i < VPL; i++) {
        s  += v[i].x + v[i].y + v[i].z + v[i].w;
        ss += v[i].x * v[i].x + v[i].y * v[i].y
            + v[i].z * v[i].z + v[i].w * v[i].w;
    }

    // Butterfly reduction: every lane ends with the full row sums
    #pragma unroll
    for (int off = 16; off > 0; off >>= 1) {
        s  += __shfl_xor_sync(0xFFFFFFFFu, s,  off);
        ss += __shfl_xor_sync(0xFFFFFFFFu, ss, off);
    }

    // Redundant per-lane scalar epilogue (FMA pipe has headroom)
    const float inv_d = 1.0f / (float)D;
    float mean = s * inv_d;
    float var  = ss * inv_d - mean * mean;
    float a = var + EPS;
    float inv_a = 1.0f / a;            // single divide
    float half_a = 0.5f * a;
    float t;
    t = fmaf(a * inv_a, 0.5f, half_a);     // l1 = (a/a + a)*0.5
    t = fmaf(t * inv_a, 0.5f, half_a);     // l2
    t = fmaf(t * inv_a, 0.5f, half_a);     // l3
    t = fmaf(t * inv_a, 0.5f, half_a);     // std
    const float rstd = 1.0f / t;

    // Fused normalize + affine, 8 float4 stores
    #pragma unroll
    for (int i = 0; i < VPL; i++) {
        const int col = (i * 32 + lane) * 4;
        float4 w = *reinterpret_cast<const float4*>(weight + col);
        float4 b = *reinterpret_cast<const float4*>(bias   + col);
        float4 o;
        o.x = (v[i].x - mean) * rstd * w.x + b.x;
        o.y = (v[i].y - mean) * rstd * w.y + b.y;
        o.z = (v[i].z - mean) * rstd * w.z + b.z;
        o.w = (v[i].w - mean) * rstd * w.w + b.w;
        *reinterpret_cast<float4*>(orow + col) = o;
    }
}

extern "C" void kernel_launch(void* const* d_in, const int* in_sizes, int n_in,
                              void* d_out, int out_size) {
    const float* x      = (const float*)d_in[0];
    const float* weight = (const float*)d_in[1];
    const float* bias   = (const float*)d_in[2];
    float* out          = (float*)d_out;

    const int rows = in_sizes[0] / D;                 // 32768
    const int grid = rows / WARPS_PER_CTA;            // 4096
    qlayernorm_kernel<<<grid, THREADS>>>(x, weight, bias, out);
}

// round 17
// speedup vs baseline: 1.1174x; 1.0007x over previous
#include <cuda_runtime.h>

// QLayerNorm: B=4, S=8192, D=1024, fp32. Champion structure (R3/R16):
// warp-per-row, row held in registers, no smem, no barriers. ncu 36.9us,
// DRAM 72.7%, 5.76 TB/s — memory-system bound at the 1:1 read/write
// turnaround point (validated against 7 structural alternatives).
// This round's single variable: __ldcs on x loads (evict-first; each x
// line is touched exactly once, so L1 residency is pure pollution vs the
// reused 8KB weight/bias working set).
//
// Reference std recurrence (divisor is ALWAYS a, not the iterate):
//   l1=(a/a+a)*.5 ; l2=(l1/a+a)*.5 ; l3=(l2/a+a)*.5 ; std=(l3/a+a)*.5
// Implemented with inv_a = 1/a computed once (fp32 delta ~1e-7, tol 1e-3).

#define D 1024
#define WARPS_PER_CTA 8
#define THREADS (WARPS_PER_CTA * 32)
#define VPL 8            // float4 loads per lane (D / (32*4))
#define EPS 5e-05f

__global__ __launch_bounds__(THREADS) void qlayernorm_kernel(
    const float* __restrict__ x,
    const float* __restrict__ weight,
    const float* __restrict__ bias,
    float* __restrict__ out)
{
    const int warp = threadIdx.x >> 5;
    const int lane = threadIdx.x & 31;
    const int row  = blockIdx.x * WARPS_PER_CTA + warp;

    const float* xr   = x   + (long long)row * D;
    float*       orow = out + (long long)row * D;

    // Front-batched streaming loads: 8 independent LDG.128.CS per lane
    float4 v[VPL];
    #pragma unroll
    for (int i = 0; i < VPL; i++) {
        v[i] = __ldcs(reinterpret_cast<const float4*>(xr + (i * 32 + lane) * 4));
    }

    // Per-lane partial sums
    float s = 0.0f, ss = 0.0f;
    #pragma unroll
    for (int i = 0; i < VPL; i++) {
        s  += v[i].x + v[i].y + v[i].z + v[i].w;
        ss += v[i].x * v[i].x + v[i].y * v[i].y
            + v[i].z * v[i].z + v[i].w * v[i].w;
    }

    // Butterfly reduction: every lane ends with the full row sums
    #pragma unroll
    for (int off = 16; off > 0; off >>= 1) {
        s  += __shfl_xor_sync(0xFFFFFFFFu, s,  off);
        ss += __shfl_xor_sync(0xFFFFFFFFu, ss, off);
    }

    // Redundant per-lane scalar epilogue (FMA pipe has headroom)
    const float inv_d = 1.0f / (float)D;
    float mean = s * inv_d;
    float var  = ss * inv_d - mean * mean;
    float a = var + EPS;
    float inv_a = 1.0f / a;            // single divide
    float half_a = 0.5f * a;
    float t;
    t = fmaf(a * inv_a, 0.5f, half_a);     // l1 = (a/a + a)*0.5
    t = fmaf(t * inv_a, 0.5f, half_a);     // l2
    t = fmaf(t * inv_a, 0.5f, half_a);     // l3
    t = fmaf(t * inv_a, 0.5f, half_a);     // std
    const float rstd = 1.0f / t;

    // Fused normalize + affine, 8 float4 stores
    #pragma unroll
    for (int i = 0; i < VPL; i++) {
        const int col = (i * 32 + lane) * 4;
        float4 w = *reinterpret_cast<const float4*>(weight + col);
        float4 b = *reinterpret_cast<const float4*>(bias   + col);
        float4 o;
        o.x = (v[i].x - mean) * rstd * w.x + b.x;
        o.y = (v[i].y - mean) * rstd * w.y + b.y;
        o.z = (v[i].z - mean) * rstd * w.z + b.z;
        o.w = (v[i].w - mean) * rstd * w.w + b.w;
        *reinterpret_cast<float4*>(orow + col) = o;
    }
}

extern "C" void kernel_launch(void* const* d_in, const int* in_sizes, int n_in,
                              void* d_out, int out_size) {
    const float* x      = (const float*)d_in[0];
    const float* weight = (const float*)d_in[1];
    const float* bias   = (const float*)d_in[2];
    float* out          = (float*)d_out;

    const int rows = in_sizes[0] / D;                 // 32768
    const int grid = rows / WARPS_PER_CTA;            // 4096
    qlayernorm_kernel<<<grid, THREADS>>>(x, weight, bias, out);
}